// round 1
// baseline (speedup 1.0000x reference)
#include <cuda_runtime.h>

#define BB 256
#define SS 512
#define EE 128
#define NWARP 16
#define THREADS 512

__global__ __launch_bounds__(THREADS, 2)
void fused_pool_kernel(const int* __restrict__ x,
                       const float* __restrict__ emb,
                       const float* __restrict__ Wq,
                       const float* __restrict__ bq,
                       const float* __restrict__ Wm,
                       const float* __restrict__ bm,
                       float* __restrict__ out)
{
    __shared__ float s_p[SS];          // log_p -> p
    __shared__ int   s_idx[SS];        // token ids for this batch row
    __shared__ float s_th[NWARP][EE];  // per-warp partial t_hat
    __shared__ float s_red[32];        // block reduction scratch

    const int b   = blockIdx.x;
    const int tid = threadIdx.x;
    const int w   = tid >> 5;
    const int l   = tid & 31;

    // cache token indices (x read exactly once)
    s_idx[tid] = x[b * SS + tid];

    // each lane keeps its 4-float chunk of Wq in registers
    const float4 wq4 = reinterpret_cast<const float4*>(Wq)[l];
    const float bq0 = bq[0];
    __syncthreads();

    // ---------------- Phase A: log_p[s] = (row . Wq + bq) * sum(row) ----------------
    // warp w handles tokens s = w, w+16, ... (32 tokens per warp)
    #pragma unroll 4
    for (int s = w; s < SS; s += NWARP) {
        const float4 v = reinterpret_cast<const float4*>(emb + (size_t)s_idx[s] * EE)[l];
        float dot = v.x * wq4.x + v.y * wq4.y + v.z * wq4.z + v.w * wq4.w;
        float sm  = (v.x + v.y) + (v.z + v.w);
        #pragma unroll
        for (int o = 16; o; o >>= 1) {
            dot += __shfl_xor_sync(0xffffffffu, dot, o);
            sm  += __shfl_xor_sync(0xffffffffu, sm,  o);
        }
        if (l == 0) s_p[s] = (dot + bq0) * sm;
    }
    __syncthreads();

    // ---------------- Phase B: softmax over S in shared memory ----------------
    const float v = s_p[tid];
    // block max
    float m = v;
    #pragma unroll
    for (int o = 16; o; o >>= 1) m = fmaxf(m, __shfl_xor_sync(0xffffffffu, m, o));
    if (l == 0) s_red[w] = m;
    __syncthreads();
    if (w == 0) {
        float mm = (l < NWARP) ? s_red[l] : -3.4e38f;
        #pragma unroll
        for (int o = 16; o; o >>= 1) mm = fmaxf(mm, __shfl_xor_sync(0xffffffffu, mm, o));
        if (l == 0) s_red[0] = mm;
    }
    __syncthreads();
    m = s_red[0];
    __syncthreads();   // everyone has read s_red[0] before reuse

    const float e = expf(v - m);
    float sum = e;
    #pragma unroll
    for (int o = 16; o; o >>= 1) sum += __shfl_xor_sync(0xffffffffu, sum, o);
    if (l == 0) s_red[w] = sum;
    __syncthreads();
    if (w == 0) {
        float ss = (l < NWARP) ? s_red[l] : 0.f;
        #pragma unroll
        for (int o = 16; o; o >>= 1) ss += __shfl_xor_sync(0xffffffffu, ss, o);
        if (l == 0) s_red[0] = ss;
    }
    __syncthreads();
    const float inv = 1.0f / s_red[0];
    s_p[tid] = e * inv;
    __syncthreads();

    // ---------------- Phase C: t_hat = sum_s p[s] * row[s] ----------------
    float4 acc = make_float4(0.f, 0.f, 0.f, 0.f);
    #pragma unroll 4
    for (int s = w; s < SS; s += NWARP) {
        const float ps = s_p[s];
        const float4 vv = reinterpret_cast<const float4*>(emb + (size_t)s_idx[s] * EE)[l];
        acc.x = fmaf(ps, vv.x, acc.x);
        acc.y = fmaf(ps, vv.y, acc.y);
        acc.z = fmaf(ps, vv.z, acc.z);
        acc.w = fmaf(ps, vv.w, acc.w);
    }
    reinterpret_cast<float4*>(&s_th[w][4 * l])[0] = acc;
    __syncthreads();

    // reduce 16 warp-partials -> t_hat[e], then MLP head + relu
    if (tid < EE) {
        float t = 0.f;
        #pragma unroll
        for (int ww = 0; ww < NWARP; ww++) t += s_th[ww][tid];
        // Phase D: out[b, j] = relu(sum_e t_hat[e] * Wm[e,j] + bm[j])
        float p0 = t * Wm[tid * 2 + 0];
        float p1 = t * Wm[tid * 2 + 1];
        #pragma unroll
        for (int o = 16; o; o >>= 1) {
            p0 += __shfl_xor_sync(0xffffffffu, p0, o);
            p1 += __shfl_xor_sync(0xffffffffu, p1, o);
        }
        if (l == 0) {
            s_red[w * 2 + 0] = p0;   // w in 0..3 here
            s_red[w * 2 + 1] = p1;
        }
    }
    __syncthreads();
    if (tid == 0) {
        float o0 = (s_red[0] + s_red[2]) + (s_red[4] + s_red[6]) + bm[0];
        float o1 = (s_red[1] + s_red[3]) + (s_red[5] + s_red[7]) + bm[1];
        out[b * 2 + 0] = fmaxf(o0, 0.f);
        out[b * 2 + 1] = fmaxf(o1, 0.f);
    }
}

extern "C" void kernel_launch(void* const* d_in, const int* in_sizes, int n_in,
                              void* d_out, int out_size)
{
    const int*   x   = (const int*)  d_in[0];
    const float* emb = (const float*)d_in[1];
    const float* Wq  = (const float*)d_in[2];
    const float* bq  = (const float*)d_in[3];
    const float* Wm  = (const float*)d_in[4];
    const float* bm  = (const float*)d_in[5];
    float* out = (float*)d_out;

    fused_pool_kernel<<<BB, THREADS>>>(x, emb, Wq, bq, Wm, bm, out);
}